// round 1
// baseline (speedup 1.0000x reference)
#include <cuda_runtime.h>
#include <cstdint>

#define LSEQ 8192
#define DIM  2048
#define NCHUNK 64
#define CHUNK 128

// Scratch (allocation-free rule: __device__ globals)
__device__ float g_xm[(size_t)LSEQ * DIM];        // 64 MB x_mix buffer (tf32-rounded)
__device__ float g_carry[NCHUNK * DIM];
__device__ float g_mprev[NCHUNK * DIM];

__device__ __forceinline__ float sigmoidf_(float p) { return 1.0f / (1.0f + expf(-p)); }

__device__ __forceinline__ float totf32(float x) {
    float r;
    asm("cvt.rna.tf32.f32 %0, %1;" : "=f"(r) : "f"(x));
    return r;
}

// ---------------------------------------------------------------------------
// Pass A: chunk-local EMA scan with zero carry-in.
//   y[t] = f*y[t-1] + (1-f)*x[t]   within each 128-step chunk
// Writes local y into g_xm, chunk-final y into g_carry.
// ---------------------------------------------------------------------------
__global__ void scan_chunk_kernel(const float* __restrict__ x,
                                  const float* __restrict__ fparam) {
    int d = blockIdx.x * blockDim.x + threadIdx.x;
    int c = blockIdx.y;
    float f = sigmoidf_(fparam[d]);
    float omf = 1.0f - f;
    const float* xp = x + (size_t)c * CHUNK * DIM + d;
    float* yp = g_xm + (size_t)c * CHUNK * DIM + d;
    float y = 0.0f;
#pragma unroll 8
    for (int i = 0; i < CHUNK; i++) {
        y = fmaf(f, y, omf * xp[(size_t)i * DIM]);
        yp[(size_t)i * DIM] = y;
    }
    g_carry[c * DIM + d] = y;
}

// ---------------------------------------------------------------------------
// Pass B: serial combine of the 64 chunk carries per dim.
//   M[c] = f^128 * M[c-1] + Y[c],  M[-1] = x_mix_last
// g_mprev[c] holds M[c-1] (the true x_mix value entering chunk c).
// ---------------------------------------------------------------------------
__global__ void carry_kernel(const float* __restrict__ fparam,
                             const float* __restrict__ xml) {
    int d = blockIdx.x * blockDim.x + threadIdx.x;
    float f = sigmoidf_(fparam[d]);
    float fC = f;
#pragma unroll
    for (int i = 0; i < 7; i++) fC *= fC;   // f^128 via repeated squaring
    float m = xml[d];
#pragma unroll 4
    for (int c = 0; c < NCHUNK; c++) {
        g_mprev[c * DIM + d] = m;
        m = fmaf(fC, m, g_carry[c * DIM + d]);
    }
}

// ---------------------------------------------------------------------------
// Pass C: fixup. x_mix[t] = y_local[t] + f^(off+1) * M_prev[chunk].
// Also pre-rounds to tf32 so the GEMM can consume A directly.
// ---------------------------------------------------------------------------
__global__ void fixup_kernel(const float* __restrict__ fparam) {
    int d = blockIdx.x * blockDim.x + threadIdx.x;
    int c = blockIdx.y;
    float f = sigmoidf_(fparam[d]);
    float mp = g_mprev[c * DIM + d];
    float p = f;
    float* yp = g_xm + (size_t)c * CHUNK * DIM + d;
#pragma unroll 8
    for (int i = 0; i < CHUNK; i++) {
        float v = fmaf(p, mp, yp[(size_t)i * DIM]);
        yp[(size_t)i * DIM] = totf32(v);
        p *= f;
    }
}

// ---------------------------------------------------------------------------
// GEMM: out[t, j] = sum_d x_mix[t, d] * W[j, d]
// A = g_xm [M=8192, K=2048] row-major, B = W [N=2048, K=2048] row-major
// (both K-major -> mma .row.col directly).
// Tile 128x128x32, 256 threads, 8 warps as 2(m) x 4(n), warp tile 64x32.
// Single smem buffer + register prefetch of the next K-tile.
// ---------------------------------------------------------------------------
constexpr int BM = 128, BN = 128, BK = 32, PAD = 4;

#define MMA_TF32(c, a, b)                                                     \
    asm volatile(                                                             \
        "mma.sync.aligned.m16n8k8.row.col.f32.tf32.tf32.f32 "                 \
        "{%0,%1,%2,%3},{%4,%5,%6,%7},{%8,%9},{%0,%1,%2,%3};\n"                \
        : "+f"((c)[0]), "+f"((c)[1]), "+f"((c)[2]), "+f"((c)[3])              \
        : "r"((a)[0]), "r"((a)[1]), "r"((a)[2]), "r"((a)[3]),                 \
          "r"((b)[0]), "r"((b)[1]))

__global__ __launch_bounds__(256, 1) void gemm_kernel(const float* __restrict__ Wt,
                                                      float* __restrict__ out) {
    __shared__ float As[BM][BK + PAD];
    __shared__ float Bs[BN][BK + PAD];

    int tid = threadIdx.x;
    int bm = blockIdx.y * BM, bn = blockIdx.x * BN;
    int lrow = tid >> 3;             // 0..31
    int lcol = (tid & 7) * 4;        // 0,4,...,28
    int warp = tid >> 5, lane = tid & 31;
    int wm = (warp & 1) * 64, wn = (warp >> 1) * 32;
    int grp = lane >> 2, tig = lane & 3;

    float acc[4][4][4] = {};
    float4 pa[4], pb[4];

    const float* Ag = g_xm;

    // prologue: load K-tile 0 and stage to smem
#pragma unroll
    for (int r = 0; r < 4; r++) {
        pa[r] = *(const float4*)(Ag + (size_t)(bm + lrow + r * 32) * DIM + lcol);
        pb[r] = *(const float4*)(Wt + (size_t)(bn + lrow + r * 32) * DIM + lcol);
    }
#pragma unroll
    for (int r = 0; r < 4; r++) {
        const float* va = (const float*)&pa[r];
        const float* vb = (const float*)&pb[r];
#pragma unroll
        for (int j = 0; j < 4; j++) {
            As[lrow + r * 32][lcol + j] = va[j];          // already tf32
            Bs[lrow + r * 32][lcol + j] = totf32(vb[j]);
        }
    }
    __syncthreads();

    for (int k0 = 0; k0 < DIM; k0 += BK) {
        bool more = (k0 + BK) < DIM;
        if (more) {
            int kn = k0 + BK;
#pragma unroll
            for (int r = 0; r < 4; r++) {
                pa[r] = *(const float4*)(Ag + (size_t)(bm + lrow + r * 32) * DIM + kn + lcol);
                pb[r] = *(const float4*)(Wt + (size_t)(bn + lrow + r * 32) * DIM + kn + lcol);
            }
        }
        // compute current smem tile
#pragma unroll
        for (int ks = 0; ks < 4; ks++) {
            int kk = ks * 8;
            unsigned a[4][4];
            unsigned b[4][2];
#pragma unroll
            for (int mt = 0; mt < 4; mt++) {
                int row = wm + mt * 16 + grp;
                a[mt][0] = __float_as_uint(As[row][kk + tig]);
                a[mt][1] = __float_as_uint(As[row + 8][kk + tig]);
                a[mt][2] = __float_as_uint(As[row][kk + tig + 4]);
                a[mt][3] = __float_as_uint(As[row + 8][kk + tig + 4]);
            }
#pragma unroll
            for (int nt = 0; nt < 4; nt++) {
                int col = wn + nt * 8 + grp;
                b[nt][0] = __float_as_uint(Bs[col][kk + tig]);
                b[nt][1] = __float_as_uint(Bs[col][kk + tig + 4]);
            }
#pragma unroll
            for (int mt = 0; mt < 4; mt++)
#pragma unroll
                for (int nt = 0; nt < 4; nt++)
                    MMA_TF32(acc[mt][nt], a[mt], b[nt]);
        }
        __syncthreads();
        if (more) {
#pragma unroll
            for (int r = 0; r < 4; r++) {
                const float* va = (const float*)&pa[r];
                const float* vb = (const float*)&pb[r];
#pragma unroll
                for (int j = 0; j < 4; j++) {
                    As[lrow + r * 32][lcol + j] = va[j];
                    Bs[lrow + r * 32][lcol + j] = totf32(vb[j]);
                }
            }
            __syncthreads();
        }
    }

    // epilogue: float2 stores
#pragma unroll
    for (int mt = 0; mt < 4; mt++) {
#pragma unroll
        for (int nt = 0; nt < 4; nt++) {
            int row = bm + wm + mt * 16 + grp;
            int col = bn + wn + nt * 8 + tig * 2;
            float2 v0 = make_float2(acc[mt][nt][0], acc[mt][nt][1]);
            float2 v1 = make_float2(acc[mt][nt][2], acc[mt][nt][3]);
            *(float2*)(out + (size_t)row * DIM + col) = v0;
            *(float2*)(out + (size_t)(row + 8) * DIM + col) = v1;
        }
    }
}

// ---------------------------------------------------------------------------
extern "C" void kernel_launch(void* const* d_in, const int* in_sizes, int n_in,
                              void* d_out, int out_size) {
    const float* x      = (const float*)d_in[0];   // [L, D]
    const float* xml    = (const float*)d_in[1];   // [D]
    const float* fparam = (const float*)d_in[2];   // [D]
    const float* Wt     = (const float*)d_in[3];   // [D, D]
    float* out = (float*)d_out;                    // [L, D]

    scan_chunk_kernel<<<dim3(DIM / 256, NCHUNK), 256>>>(x, fparam);
    carry_kernel<<<DIM / 256, 256>>>(fparam, xml);
    fixup_kernel<<<dim3(DIM / 256, NCHUNK), 256>>>(fparam);
    gemm_kernel<<<dim3(DIM / BN, LSEQ / BM), 256>>>(Wt, out);
}

// round 7
// speedup vs baseline: 1.3408x; 1.3408x over previous
#include <cuda_runtime.h>
#include <cstdint>

#define LSEQ 8192
#define DIM  2048
#define NCHUNK 64
#define CHUNK 128

// ---------------- scratch (__device__ globals; no allocation) ---------------
__device__ float g_xm[(size_t)LSEQ * DIM];     // x_mix, tf32-rounded
__device__ float g_wtf[(size_t)DIM * DIM];     // W, tf32-rounded
__device__ float g_carry[NCHUNK * DIM];
__device__ float g_mprev[NCHUNK * DIM];

__device__ __forceinline__ float sigmoidf_(float p) { return 1.0f / (1.0f + expf(-p)); }
__device__ __forceinline__ float totf32(float x) {
    float r; asm("cvt.rna.tf32.f32 %0, %1;" : "=f"(r) : "f"(x)); return r;
}

// ---------------------------------------------------------------------------
// Pass A: per-chunk carry only (zero-seeded local scan, no intermediate stores)
// ---------------------------------------------------------------------------
__global__ void carryscan_kernel(const float* __restrict__ x,
                                 const float* __restrict__ fparam) {
    int d = blockIdx.x * blockDim.x + threadIdx.x;
    int c = blockIdx.y;
    float f = sigmoidf_(fparam[d]);
    float omf = 1.0f - f;
    const float* xp = x + (size_t)c * CHUNK * DIM + d;
    float y = 0.0f;
#pragma unroll 8
    for (int i = 0; i < CHUNK; i++)
        y = fmaf(f, y, omf * xp[(size_t)i * DIM]);
    g_carry[c * DIM + d] = y;
}

// ---------------------------------------------------------------------------
// Pass B: serial combine of chunk carries. g_mprev[c] = m value entering chunk c.
// ---------------------------------------------------------------------------
__global__ void carry_kernel(const float* __restrict__ fparam,
                             const float* __restrict__ xml) {
    int d = blockIdx.x * blockDim.x + threadIdx.x;
    float f = sigmoidf_(fparam[d]);
    float fC = f;
#pragma unroll
    for (int i = 0; i < 7; i++) fC *= fC;   // f^128
    float m = xml[d];
#pragma unroll 4
    for (int c = 0; c < NCHUNK; c++) {
        g_mprev[c * DIM + d] = m;
        m = fmaf(fC, m, g_carry[c * DIM + d]);
    }
}

// ---------------------------------------------------------------------------
// Pass C: seeded rescan, writes tf32-rounded x_mix.
//   y_{-1} = mprev;  y_t = f*y_{t-1} + (1-f)*x_t
// ---------------------------------------------------------------------------
__global__ void scan_write_kernel(const float* __restrict__ x,
                                  const float* __restrict__ fparam) {
    int d = blockIdx.x * blockDim.x + threadIdx.x;
    int c = blockIdx.y;
    float f = sigmoidf_(fparam[d]);
    float omf = 1.0f - f;
    const float* xp = x + (size_t)c * CHUNK * DIM + d;
    float* yp = g_xm + (size_t)c * CHUNK * DIM + d;
    float y = g_mprev[c * DIM + d];
#pragma unroll 8
    for (int i = 0; i < CHUNK; i++) {
        y = fmaf(f, y, omf * xp[(size_t)i * DIM]);
        yp[(size_t)i * DIM] = totf32(y);
    }
}

// W -> tf32-rounded copy (rna; HW mma truncation would be RZ)
__global__ void wconv_kernel(const float* __restrict__ W) {
    int i = blockIdx.x * blockDim.x + threadIdx.x;
    float4 v = ((const float4*)W)[i];
    v.x = totf32(v.x); v.y = totf32(v.y); v.z = totf32(v.z); v.w = totf32(v.w);
    ((float4*)g_wtf)[i] = v;
}

// ---------------------------------------------------------------------------
// Legacy-HMMA tf32 GEMM:  out[m,n] = sum_k A[m,k] * W[n,k]
// Block 256x128x32, 256 threads = 8 warps as 4(m) x 2(n), warp tile 64x64.
// cp.async double-buffered smem, padded rows (stride 36 floats) for
// conflict-free fragment loads.
// ---------------------------------------------------------------------------
#define BM 256
#define BN 128
#define BK 32
#define KTILES (DIM / BK)
#define RS 36                            // row stride in floats (32 + 4 pad)
#define A_FLOATS (BM * RS)               // 9216
#define B_FLOATS (BN * RS)               // 4608
#define STAGE_FLOATS (A_FLOATS + B_FLOATS)  // 13824
#define SM_BYTES (2 * STAGE_FLOATS * 4)  // 110592

#define MMA_TF32(c, a, b)                                                     \
    asm volatile(                                                             \
        "mma.sync.aligned.m16n8k8.row.col.f32.tf32.tf32.f32 "                 \
        "{%0,%1,%2,%3},{%4,%5,%6,%7},{%8,%9},{%0,%1,%2,%3};\n"                \
        : "+f"((c)[0]), "+f"((c)[1]), "+f"((c)[2]), "+f"((c)[3])              \
        : "r"((a)[0]), "r"((a)[1]), "r"((a)[2]), "r"((a)[3]),                 \
          "r"((b)[0]), "r"((b)[1]))

__device__ __forceinline__ uint32_t smem_u32(const void* p) {
    uint32_t a;
    asm("{ .reg .u64 t; cvta.to.shared.u64 t, %1; cvt.u32.u64 %0, t; }" : "=r"(a) : "l"(p));
    return a;
}
__device__ __forceinline__ void cp16(uint32_t dst, const void* src) {
    asm volatile("cp.async.cg.shared.global [%0], [%1], 16;" :: "r"(dst), "l"(src));
}
__device__ __forceinline__ void cp_commit() {
    asm volatile("cp.async.commit_group;");
}
template <int N>
__device__ __forceinline__ void cp_wait() {
    asm volatile("cp.async.wait_group %0;" :: "n"(N));
}

__global__ __launch_bounds__(256, 1) void gemm_kernel(float* __restrict__ out) {
    extern __shared__ float sm[];
    uint32_t sb = smem_u32(sm);

    int tid = threadIdx.x;
    int bm = blockIdx.y * BM, bn = blockIdx.x * BN;
    int warp = tid >> 5, lane = tid & 31;
    int wm = (warp & 3) * 64, wn = (warp >> 2) * 64;
    int grp = lane >> 2, tig = lane & 3;

    int lrow = tid >> 3;            // 0..31
    int lc4 = tid & 7;              // float4 column 0..7

    const float* Ag = g_xm + (size_t)bm * DIM;
    const float* Bg = g_wtf + (size_t)bn * DIM;

    float acc[4][8][4] = {};

    // ---- prologue: load ktile 0 into stage 0 ----
    {
        uint32_t aB = sb;
        uint32_t bB = sb + A_FLOATS * 4;
#pragma unroll
        for (int o = 0; o < 8; o++) {
            int row = lrow + o * 32;
            cp16(aB + (row * RS + lc4 * 4) * 4, Ag + (size_t)row * DIM + lc4 * 4);
        }
#pragma unroll
        for (int o = 0; o < 4; o++) {
            int row = lrow + o * 32;
            cp16(bB + (row * RS + lc4 * 4) * 4, Bg + (size_t)row * DIM + lc4 * 4);
        }
        cp_commit();
    }

    for (int j = 0; j < KTILES; j++) {
        int cur = j & 1;
        // ---- issue loads for ktile j+1 into the other stage ----
        if (j + 1 < KTILES) {
            int nxt = cur ^ 1;
            int kc = (j + 1) * BK;
            uint32_t aB = sb + (nxt * STAGE_FLOATS) * 4;
            uint32_t bB = sb + (nxt * STAGE_FLOATS + A_FLOATS) * 4;
            const float* Ak = Ag + kc;
            const float* Bk = Bg + kc;
#pragma unroll
            for (int o = 0; o < 8; o++) {
                int row = lrow + o * 32;
                cp16(aB + (row * RS + lc4 * 4) * 4, Ak + (size_t)row * DIM + lc4 * 4);
            }
#pragma unroll
            for (int o = 0; o < 4; o++) {
                int row = lrow + o * 32;
                cp16(bB + (row * RS + lc4 * 4) * 4, Bk + (size_t)row * DIM + lc4 * 4);
            }
            cp_commit();
            cp_wait<1>();
        } else {
            cp_wait<0>();
        }
        __syncthreads();

        // ---- compute current stage ----
        const float* As = sm + cur * STAGE_FLOATS;
        const float* Bs = As + A_FLOATS;
#pragma unroll
        for (int ks = 0; ks < 4; ks++) {
            int kk = ks * 8;
            unsigned a[4][4];
            unsigned b[8][2];
#pragma unroll
            for (int mt = 0; mt < 4; mt++) {
                int row = wm + mt * 16 + grp;
                a[mt][0] = __float_as_uint(As[row * RS + kk + tig]);
                a[mt][1] = __float_as_uint(As[(row + 8) * RS + kk + tig]);
                a[mt][2] = __float_as_uint(As[row * RS + kk + tig + 4]);
                a[mt][3] = __float_as_uint(As[(row + 8) * RS + kk + tig + 4]);
            }
#pragma unroll
            for (int nt = 0; nt < 8; nt++) {
                int col = wn + nt * 8 + grp;
                b[nt][0] = __float_as_uint(Bs[col * RS + kk + tig]);
                b[nt][1] = __float_as_uint(Bs[col * RS + kk + tig + 4]);
            }
#pragma unroll
            for (int mt = 0; mt < 4; mt++)
#pragma unroll
                for (int nt = 0; nt < 8; nt++)
                    MMA_TF32(acc[mt][nt], a[mt], b[nt]);
        }
        __syncthreads();
    }

    // ---- epilogue: float2 stores ----
#pragma unroll
    for (int mt = 0; mt < 4; mt++) {
#pragma unroll
        for (int nt = 0; nt < 8; nt++) {
            int row = bm + wm + mt * 16 + grp;
            int col = bn + wn + nt * 8 + tig * 2;
            float2 v0 = make_float2(acc[mt][nt][0], acc[mt][nt][1]);
            float2 v1 = make_float2(acc[mt][nt][2], acc[mt][nt][3]);
            *(float2*)(out + (size_t)row * DIM + col) = v0;
            *(float2*)(out + (size_t)(row + 8) * DIM + col) = v1;
        }
    }
}

// ---------------------------------------------------------------------------
extern "C" void kernel_launch(void* const* d_in, const int* in_sizes, int n_in,
                              void* d_out, int out_size) {
    const float* x      = (const float*)d_in[0];
    const float* xml    = (const float*)d_in[1];
    const float* fparam = (const float*)d_in[2];
    const float* W      = (const float*)d_in[3];
    float* out = (float*)d_out;

    carryscan_kernel<<<dim3(DIM / 256, NCHUNK), 256>>>(x, fparam);
    carry_kernel<<<DIM / 256, 256>>>(fparam, xml);
    scan_write_kernel<<<dim3(DIM / 256, NCHUNK), 256>>>(x, fparam);
    wconv_kernel<<<(DIM * DIM / 4) / 256, 256>>>(W);

    static bool attr_set = false;
    if (!attr_set) {
        cudaFuncSetAttribute(gemm_kernel, cudaFuncAttributeMaxDynamicSharedMemorySize, SM_BYTES);
        attr_set = true;
    }
    gemm_kernel<<<dim3(DIM / BN, LSEQ / BM), 256, SM_BYTES>>>(out);
}

// round 8
// speedup vs baseline: 1.4766x; 1.1012x over previous
#include <cuda_runtime.h>
#include <cstdint>

#define LSEQ 8192
#define DIM  2048
#define NCHUNK 64
#define CHUNK 128

// ---------------- scratch (__device__ globals; no allocation) ---------------
__device__ float g_xm[(size_t)LSEQ * DIM];     // x_mix, tf32-rounded
__device__ float g_wtf[(size_t)DIM * DIM];     // W, tf32-rounded
__device__ float g_carry[NCHUNK * DIM];
__device__ float g_mprev[NCHUNK * DIM];

__device__ __forceinline__ float sigmoidf_(float p) { return 1.0f / (1.0f + expf(-p)); }
__device__ __forceinline__ float totf32(float x) {
    float r; asm("cvt.rna.tf32.f32 %0, %1;" : "=f"(r) : "f"(x)); return r;
}

// ---------------------------------------------------------------------------
// Pass A: per-chunk carry only (zero-seeded local scan)
// ---------------------------------------------------------------------------
__global__ void carryscan_kernel(const float* __restrict__ x,
                                 const float* __restrict__ fparam) {
    int d = blockIdx.x * blockDim.x + threadIdx.x;
    int c = blockIdx.y;
    float f = sigmoidf_(fparam[d]);
    float omf = 1.0f - f;
    const float* xp = x + (size_t)c * CHUNK * DIM + d;
    float y = 0.0f;
#pragma unroll 8
    for (int i = 0; i < CHUNK; i++)
        y = fmaf(f, y, omf * xp[(size_t)i * DIM]);
    g_carry[c * DIM + d] = y;
}

// ---------------------------------------------------------------------------
// Pass B: serial combine of chunk carries.
// ---------------------------------------------------------------------------
__global__ void carry_kernel(const float* __restrict__ fparam,
                             const float* __restrict__ xml) {
    int d = blockIdx.x * blockDim.x + threadIdx.x;
    float f = sigmoidf_(fparam[d]);
    float fC = f;
#pragma unroll
    for (int i = 0; i < 7; i++) fC *= fC;   // f^128
    float m = xml[d];
#pragma unroll 4
    for (int c = 0; c < NCHUNK; c++) {
        g_mprev[c * DIM + d] = m;
        m = fmaf(fC, m, g_carry[c * DIM + d]);
    }
}

// ---------------------------------------------------------------------------
// Pass C: seeded rescan, writes tf32-rounded x_mix.
// ---------------------------------------------------------------------------
__global__ void scan_write_kernel(const float* __restrict__ x,
                                  const float* __restrict__ fparam) {
    int d = blockIdx.x * blockDim.x + threadIdx.x;
    int c = blockIdx.y;
    float f = sigmoidf_(fparam[d]);
    float omf = 1.0f - f;
    const float* xp = x + (size_t)c * CHUNK * DIM + d;
    float* yp = g_xm + (size_t)c * CHUNK * DIM + d;
    float y = g_mprev[c * DIM + d];
#pragma unroll 8
    for (int i = 0; i < CHUNK; i++) {
        y = fmaf(f, y, omf * xp[(size_t)i * DIM]);
        yp[(size_t)i * DIM] = totf32(y);
    }
}

// W -> tf32-rounded copy
__global__ void wconv_kernel(const float* __restrict__ W) {
    int i = blockIdx.x * blockDim.x + threadIdx.x;
    float4 v = ((const float4*)W)[i];
    v.x = totf32(v.x); v.y = totf32(v.y); v.z = totf32(v.z); v.w = totf32(v.w);
    ((float4*)g_wtf)[i] = v;
}

// ---------------------------------------------------------------------------
// tf32 mma.sync GEMM:  out[m,n] = sum_k A[m,k] * W[n,k]
// Block 256x128x32, 256 threads = 8 warps (4m x 2n), warp tile 64x64.
// 4-stage cp.async ring (prefetch distance 2, single barrier per ktile),
// register double-buffered fragments (LDS of ks+1 overlaps MMA of ks).
// ---------------------------------------------------------------------------
#define BM 256
#define BN 128
#define BK 32
#define KTILES (DIM / BK)
#define RS 36                                 // row stride in floats
#define A_FLOATS (BM * RS)                    // 9216
#define B_FLOATS (BN * RS)                    // 4608
#define STAGE_FLOATS (A_FLOATS + B_FLOATS)    // 13824
#define NSTAGE 4
#define SM_BYTES (NSTAGE * STAGE_FLOATS * 4)  // 221184

#define MMA_TF32(c, a, b)                                                     \
    asm volatile(                                                             \
        "mma.sync.aligned.m16n8k8.row.col.f32.tf32.tf32.f32 "                 \
        "{%0,%1,%2,%3},{%4,%5,%6,%7},{%8,%9},{%0,%1,%2,%3};\n"                \
        : "+f"((c)[0]), "+f"((c)[1]), "+f"((c)[2]), "+f"((c)[3])              \
        : "r"((a)[0]), "r"((a)[1]), "r"((a)[2]), "r"((a)[3]),                 \
          "r"((b)[0]), "r"((b)[1]))

__device__ __forceinline__ uint32_t smem_u32(const void* p) {
    uint32_t a;
    asm("{ .reg .u64 t; cvta.to.shared.u64 t, %1; cvt.u32.u64 %0, t; }" : "=r"(a) : "l"(p));
    return a;
}
__device__ __forceinline__ void cp16(uint32_t dst, const void* src) {
    asm volatile("cp.async.cg.shared.global [%0], [%1], 16;" :: "r"(dst), "l"(src));
}
__device__ __forceinline__ void cp_commit() {
    asm volatile("cp.async.commit_group;");
}
template <int N>
__device__ __forceinline__ void cp_wait() {
    asm volatile("cp.async.wait_group %0;" :: "n"(N));
}

__global__ __launch_bounds__(256, 1) void gemm_kernel(float* __restrict__ out) {
    extern __shared__ float sm[];
    uint32_t sb = smem_u32(sm);

    int tid = threadIdx.x;
    int bm = blockIdx.y * BM, bn = blockIdx.x * BN;
    int warp = tid >> 5, lane = tid & 31;
    int wm = (warp & 3) * 64, wn = (warp >> 2) * 64;
    int grp = lane >> 2, tig = lane & 3;

    int lrow = tid >> 3;            // 0..31
    int lc4 = tid & 7;              // float4 column 0..7

    const float* Ag = g_xm + (size_t)bm * DIM + lc4 * 4 + (size_t)lrow * DIM;
    const float* Bg = g_wtf + (size_t)bn * DIM + lc4 * 4 + (size_t)lrow * DIM;
    uint32_t stoffA = ((lrow * RS + lc4 * 4) * 4);
    uint32_t stoffB = ((lrow * RS + lc4 * 4) * 4) + A_FLOATS * 4;

    float acc[4][8][4] = {};

    // issue loads for ktile t into ring slot t%NSTAGE
    auto issue = [&](int t) {
        uint32_t base = sb + (t & (NSTAGE - 1)) * (STAGE_FLOATS * 4);
        const float* Ak = Ag + t * BK;
        const float* Bk = Bg + t * BK;
#pragma unroll
        for (int o = 0; o < 8; o++)
            cp16(base + stoffA + o * (32 * RS * 4), Ak + (size_t)(o * 32) * DIM);
#pragma unroll
        for (int o = 0; o < 4; o++)
            cp16(base + stoffB + o * (32 * RS * 4), Bk + (size_t)(o * 32) * DIM);
        cp_commit();
    };

    issue(0);
    issue(1);

    for (int j = 0; j < KTILES; j++) {
        if (j + 2 < KTILES) { issue(j + 2); cp_wait<2>(); }
        else if (j + 1 < KTILES) { cp_wait<1>(); }
        else { cp_wait<0>(); }
        __syncthreads();   // single barrier: orders stage-j visibility AND
                           // protects slot (j+2)%4 (last read at iter j-2)

        const float* As = sm + (j & (NSTAGE - 1)) * STAGE_FLOATS;
        const float* Bs = As + A_FLOATS;

        unsigned a[2][4][4], b[2][8][2];
        // prime ks=0 fragments
#pragma unroll
        for (int mt = 0; mt < 4; mt++) {
            int row = wm + mt * 16 + grp;
            a[0][mt][0] = __float_as_uint(As[row * RS + tig]);
            a[0][mt][1] = __float_as_uint(As[(row + 8) * RS + tig]);
            a[0][mt][2] = __float_as_uint(As[row * RS + tig + 4]);
            a[0][mt][3] = __float_as_uint(As[(row + 8) * RS + tig + 4]);
        }
#pragma unroll
        for (int nt = 0; nt < 8; nt++) {
            int col = wn + nt * 8 + grp;
            b[0][nt][0] = __float_as_uint(Bs[col * RS + tig]);
            b[0][nt][1] = __float_as_uint(Bs[col * RS + tig + 4]);
        }

#pragma unroll
        for (int ks = 0; ks < 4; ks++) {
            int cur = ks & 1, nxt = cur ^ 1;
            if (ks < 3) {
                int kk = (ks + 1) * 8;
#pragma unroll
                for (int mt = 0; mt < 4; mt++) {
                    int row = wm + mt * 16 + grp;
                    a[nxt][mt][0] = __float_as_uint(As[row * RS + kk + tig]);
                    a[nxt][mt][1] = __float_as_uint(As[(row + 8) * RS + kk + tig]);
                    a[nxt][mt][2] = __float_as_uint(As[row * RS + kk + tig + 4]);
                    a[nxt][mt][3] = __float_as_uint(As[(row + 8) * RS + kk + tig + 4]);
                }
#pragma unroll
                for (int nt = 0; nt < 8; nt++) {
                    int col = wn + nt * 8 + grp;
                    b[nxt][nt][0] = __float_as_uint(Bs[col * RS + kk + tig]);
                    b[nxt][nt][1] = __float_as_uint(Bs[col * RS + kk + tig + 4]);
                }
            }
#pragma unroll
            for (int mt = 0; mt < 4; mt++)
#pragma unroll
                for (int nt = 0; nt < 8; nt++)
                    MMA_TF32(acc[mt][nt], a[cur][mt], b[cur][nt]);
        }
    }

    // ---- epilogue: float2 stores ----
#pragma unroll
    for (int mt = 0; mt < 4; mt++) {
#pragma unroll
        for (int nt = 0; nt < 8; nt++) {
            int row = bm + wm + mt * 16 + grp;
            int col = bn + wn + nt * 8 + tig * 2;
            float2 v0 = make_float2(acc[mt][nt][0], acc[mt][nt][1]);
            float2 v1 = make_float2(acc[mt][nt][2], acc[mt][nt][3]);
            *(float2*)(out + (size_t)row * DIM + col) = v0;
            *(float2*)(out + (size_t)(row + 8) * DIM + col) = v1;
        }
    }
}

// ---------------------------------------------------------------------------
extern "C" void kernel_launch(void* const* d_in, const int* in_sizes, int n_in,
                              void* d_out, int out_size) {
    const float* x      = (const float*)d_in[0];
    const float* xml    = (const float*)d_in[1];
    const float* fparam = (const float*)d_in[2];
    const float* W      = (const float*)d_in[3];
    float* out = (float*)d_out;

    carryscan_kernel<<<dim3(DIM / 256, NCHUNK), 256>>>(x, fparam);
    carry_kernel<<<DIM / 256, 256>>>(fparam, xml);
    scan_write_kernel<<<dim3(DIM / 256, NCHUNK), 256>>>(x, fparam);
    wconv_kernel<<<(DIM * DIM / 4) / 256, 256>>>(W);

    static bool attr_set = false;
    if (!attr_set) {
        cudaFuncSetAttribute(gemm_kernel, cudaFuncAttributeMaxDynamicSharedMemorySize, SM_BYTES);
        attr_set = true;
    }
    gemm_kernel<<<dim3(DIM / BN, LSEQ / BM), 256, SM_BYTES>>>(out);
}

// round 9
// speedup vs baseline: 2.8881x; 1.9560x over previous
#include <cuda_runtime.h>
#include <cuda_fp16.h>
#include <cstdint>

#define LSEQ 8192
#define DIM  2048
#define NCHUNK 64
#define CHUNK 128

// ---------------- scratch (__device__ globals; no allocation) ---------------
__device__ __half g_xmh[(size_t)LSEQ * DIM];   // x_mix, fp16
__device__ __half g_wh[(size_t)DIM * DIM];     // W, fp16
__device__ float g_carry[NCHUNK * DIM];
__device__ float g_mprev[NCHUNK * DIM];

__device__ __forceinline__ float sigmoidf_(float p) { return 1.0f / (1.0f + expf(-p)); }

// ---------------------------------------------------------------------------
// Pass A: per-chunk carry only (zero-seeded local scan)
// ---------------------------------------------------------------------------
__global__ void carryscan_kernel(const float* __restrict__ x,
                                 const float* __restrict__ fparam) {
    int d = blockIdx.x * blockDim.x + threadIdx.x;
    int c = blockIdx.y;
    float f = sigmoidf_(fparam[d]);
    float omf = 1.0f - f;
    const float* xp = x + (size_t)c * CHUNK * DIM + d;
    float y = 0.0f;
#pragma unroll 8
    for (int i = 0; i < CHUNK; i++)
        y = fmaf(f, y, omf * xp[(size_t)i * DIM]);
    g_carry[c * DIM + d] = y;
}

// ---------------------------------------------------------------------------
// Pass B: serial combine of chunk carries.
// ---------------------------------------------------------------------------
__global__ void carry_kernel(const float* __restrict__ fparam,
                             const float* __restrict__ xml) {
    int d = blockIdx.x * blockDim.x + threadIdx.x;
    float f = sigmoidf_(fparam[d]);
    float fC = f;
#pragma unroll
    for (int i = 0; i < 7; i++) fC *= fC;   // f^128
    float m = xml[d];
#pragma unroll 4
    for (int c = 0; c < NCHUNK; c++) {
        g_mprev[c * DIM + d] = m;
        m = fmaf(fC, m, g_carry[c * DIM + d]);
    }
}

// ---------------------------------------------------------------------------
// Pass C: seeded rescan, writes fp16 x_mix.
// ---------------------------------------------------------------------------
__global__ void scan_write_kernel(const float* __restrict__ x,
                                  const float* __restrict__ fparam) {
    int d = blockIdx.x * blockDim.x + threadIdx.x;
    int c = blockIdx.y;
    float f = sigmoidf_(fparam[d]);
    float omf = 1.0f - f;
    const float* xp = x + (size_t)c * CHUNK * DIM + d;
    __half* yp = g_xmh + (size_t)c * CHUNK * DIM + d;
    float y = g_mprev[c * DIM + d];
#pragma unroll 8
    for (int i = 0; i < CHUNK; i++) {
        y = fmaf(f, y, omf * xp[(size_t)i * DIM]);
        yp[(size_t)i * DIM] = __float2half_rn(y);
    }
}

// W -> fp16 copy
__global__ void wconv_kernel(const float* __restrict__ W) {
    int i = blockIdx.x * blockDim.x + threadIdx.x;
    float4 v = ((const float4*)W)[i];
    __half2 h0 = __floats2half2_rn(v.x, v.y);
    __half2 h1 = __floats2half2_rn(v.z, v.w);
    ((__half2*)g_wh)[i * 2] = h0;
    ((__half2*)g_wh)[i * 2 + 1] = h1;
}

// ---------------------------------------------------------------------------
// fp16 mma.sync GEMM:  out[m,n] = sum_k A[m,k] * W[n,k]  (fp32 accum)
// Block 256x128x64, 256 threads = 8 warps (4m x 2n), warp tile 64x64.
// mma.m16n8k16, ldmatrix.x4 fragment loads, XOR-swizzled 128B smem rows,
// 4-stage cp.async ring (prefetch distance 2, one barrier per ktile),
// register double-buffered fragments.
// ---------------------------------------------------------------------------
#define BM 256
#define BN 128
#define BK 64                                  // halfs; 128 bytes per row
#define KTILES (DIM / BK)                      // 32
#define A_BYTES (BM * 128)                     // 32768
#define B_BYTES (BN * 128)                     // 16384
#define STAGE_BYTES (A_BYTES + B_BYTES)        // 49152
#define NSTAGE 4
#define SM_BYTES (NSTAGE * STAGE_BYTES)        // 196608

#define MMA_F16(c, a, b0, b1)                                                 \
    asm volatile(                                                             \
        "mma.sync.aligned.m16n8k16.row.col.f32.f16.f16.f32 "                  \
        "{%0,%1,%2,%3},{%4,%5,%6,%7},{%8,%9},{%0,%1,%2,%3};\n"                \
        : "+f"((c)[0]), "+f"((c)[1]), "+f"((c)[2]), "+f"((c)[3])              \
        : "r"((a)[0]), "r"((a)[1]), "r"((a)[2]), "r"((a)[3]),                 \
          "r"(b0), "r"(b1))

__device__ __forceinline__ uint32_t smem_u32(const void* p) {
    uint32_t a;
    asm("{ .reg .u64 t; cvta.to.shared.u64 t, %1; cvt.u32.u64 %0, t; }" : "=r"(a) : "l"(p));
    return a;
}
__device__ __forceinline__ void cp16(uint32_t dst, const void* src) {
    asm volatile("cp.async.cg.shared.global [%0], [%1], 16;" :: "r"(dst), "l"(src));
}
__device__ __forceinline__ void cp_commit() {
    asm volatile("cp.async.commit_group;");
}
template <int N>
__device__ __forceinline__ void cp_wait() {
    asm volatile("cp.async.wait_group %0;" :: "n"(N));
}
__device__ __forceinline__ void ldsm4(unsigned* r, uint32_t addr) {
    asm volatile("ldmatrix.sync.aligned.m8n8.x4.shared.b16 {%0,%1,%2,%3}, [%4];"
                 : "=r"(r[0]), "=r"(r[1]), "=r"(r[2]), "=r"(r[3]) : "r"(addr));
}

__global__ __launch_bounds__(256, 1) void gemm_kernel(float* __restrict__ out) {
    extern __shared__ char smc[];
    uint32_t sb = smem_u32(smc);

    int tid = threadIdx.x;
    int bm = blockIdx.y * BM, bn = blockIdx.x * BN;
    int warp = tid >> 5, lane = tid & 31;
    int wm = (warp & 3) * 64, wn = (warp >> 2) * 64;
    int grp = lane >> 2, tig = lane & 3;

    // cp.async thread mapping: 16B chunks, swizzle chunk ^= row&7
    int lrow = tid >> 3;            // 0..31
    int lch = tid & 7;              // chunk 0..7
    uint32_t stoffA = lrow * 128 + ((lch ^ (lrow & 7)) << 4);
    uint32_t stoffB = A_BYTES + stoffA;

    const __half* Ag = g_xmh + (size_t)(bm + lrow) * DIM + lch * 8;
    const __half* Bg = g_wh + (size_t)(bn + lrow) * DIM + lch * 8;

    // ldmatrix per-lane address components
    // A fragment (m16k16, x4): matrix mi = lane>>3:
    //   mi0: rows +0..7 kc even; mi1: rows +8 kc even; mi2: rows 0..7 kc odd; mi3: rows+8 kc odd
    uint32_t aBase[4]; int aR7[4];
    int aCC = lane >> 4;            // 0/1 -> kc parity offset
    {
        int r = (lane & 7) + ((lane >> 3) & 1) * 8;
#pragma unroll
        for (int mt = 0; mt < 4; mt++) {
            int row = wm + mt * 16 + r;
            aBase[mt] = row * 128;
            aR7[mt] = row & 7;
        }
    }
    // B fragments (two n8k16 per x4): mi0: n+0..7 kc even; mi1: n0..7 kc odd;
    //   mi2: n+8..15 kc even; mi3: n+8..15 kc odd
    uint32_t bBase[4]; int bR7[4];
    int bCC = (lane >> 3) & 1;
    {
        int r = (lane & 7) + ((lane >> 4) & 1) * 8;
#pragma unroll
        for (int p = 0; p < 4; p++) {
            int row = wn + p * 16 + r;
            bBase[p] = A_BYTES + row * 128;
            bR7[p] = row & 7;
        }
    }

    float acc[4][8][4] = {};

    auto issue = [&](int t) {
        uint32_t base = sb + (t & (NSTAGE - 1)) * STAGE_BYTES;
        const __half* Ak = Ag + t * BK;
        const __half* Bk = Bg + t * BK;
#pragma unroll
        for (int o = 0; o < 8; o++)
            cp16(base + stoffA + o * (32 * 128), Ak + (size_t)(o * 32) * DIM);
#pragma unroll
        for (int o = 0; o < 4; o++)
            cp16(base + stoffB + o * (32 * 128), Bk + (size_t)(o * 32) * DIM);
        cp_commit();
    };

    issue(0);
    issue(1);

    for (int j = 0; j < KTILES; j++) {
        if (j + 2 < KTILES) { issue(j + 2); cp_wait<2>(); }
        else if (j + 1 < KTILES) { cp_wait<1>(); }
        else { cp_wait<0>(); }
        __syncthreads();   // orders stage-j visibility; protects slot (j+2)%4
                           // (last read at iter j-2)

        uint32_t st = sb + (j & (NSTAGE - 1)) * STAGE_BYTES;

        unsigned a[2][4][4], b[2][4][4];
        // prime ks=0 fragments (kc = 0/1)
#pragma unroll
        for (int mt = 0; mt < 4; mt++)
            ldsm4(a[0][mt], st + aBase[mt] + ((aCC ^ aR7[mt]) << 4));
#pragma unroll
        for (int p = 0; p < 4; p++)
            ldsm4(b[0][p], st + bBase[p] + ((bCC ^ bR7[p]) << 4));

#pragma unroll
        for (int ks = 0; ks < 4; ks++) {
            int cur = ks & 1, nxt = cur ^ 1;
            if (ks < 3) {
                int kc = 2 * (ks + 1);
#pragma unroll
                for (int mt = 0; mt < 4; mt++)
                    ldsm4(a[nxt][mt], st + aBase[mt] + (((kc + aCC) ^ aR7[mt]) << 4));
#pragma unroll
                for (int p = 0; p < 4; p++)
                    ldsm4(b[nxt][p], st + bBase[p] + (((kc + bCC) ^ bR7[p]) << 4));
            }
#pragma unroll
            for (int mt = 0; mt < 4; mt++)
#pragma unroll
                for (int p = 0; p < 4; p++) {
                    MMA_F16(acc[mt][2 * p], a[cur][mt], b[cur][p][0], b[cur][p][1]);
                    MMA_F16(acc[mt][2 * p + 1], a[cur][mt], b[cur][p][2], b[cur][p][3]);
                }
        }
    }

    // ---- epilogue: float2 stores ----
#pragma unroll
    for (int mt = 0; mt < 4; mt++) {
#pragma unroll
        for (int nt = 0; nt < 8; nt++) {
            int row = bm + wm + mt * 16 + grp;
            int col = bn + wn + nt * 8 + tig * 2;
            float2 v0 = make_float2(acc[mt][nt][0], acc[mt][nt][1]);
            float2 v1 = make_float2(acc[mt][nt][2], acc[mt][nt][3]);
            *(float2*)(out + (size_t)row * DIM + col) = v0;
            *(float2*)(out + (size_t)(row + 8) * DIM + col) = v1;
        }
    }
}

// ---------------------------------------------------------------------------
extern "C" void kernel_launch(void* const* d_in, const int* in_sizes, int n_in,
                              void* d_out, int out_size) {
    const float* x      = (const float*)d_in[0];
    const float* xml    = (const float*)d_in[1];
    const float* fparam = (const float*)d_in[2];
    const float* W      = (const float*)d_in[3];
    float* out = (float*)d_out;

    carryscan_kernel<<<dim3(DIM / 256, NCHUNK), 256>>>(x, fparam);
    carry_kernel<<<DIM / 256, 256>>>(fparam, xml);
    scan_write_kernel<<<dim3(DIM / 256, NCHUNK), 256>>>(x, fparam);
    wconv_kernel<<<(DIM * DIM / 4) / 256, 256>>>(W);

    static bool attr_set = false;
    if (!attr_set) {
        cudaFuncSetAttribute(gemm_kernel, cudaFuncAttributeMaxDynamicSharedMemorySize, SM_BYTES);
        attr_set = true;
    }
    gemm_kernel<<<dim3(DIM / BN, LSEQ / BM), 256, SM_BYTES>>>(out);
}